// round 1
// baseline (speedup 1.0000x reference)
#include <cuda_runtime.h>
#include <math.h>

#define T_TOK 16384
#define DH 768
#define FF 2048
#define NE 8
#define BM 128
#define BN 128
#define BK 16
#define MAXROWS (2*T_TOK + NE*BM)   /* 33792: every expert segment padded to BM */

// ---------------- scratch (static __device__; no allocations allowed) ----------------
__device__ __align__(256) float g_H13[(size_t)T_TOK * 2 * FF];   // [T, 4096] w1|w3 pre-act
__device__ __align__(256) float g_Act[(size_t)T_TOK * FF];       // gelu(h1)*h3
__device__ __align__(256) float g_Hr [(size_t)MAXROWS * FF];     // routed fc1 output (post-gelu)
__device__ __align__(256) float g_Y  [(size_t)MAXROWS * DH];     // routed fc2 output * gate weight
__device__ int   g_rowtok[MAXROWS];
__device__ float g_roww  [MAXROWS];
__device__ int   g_tok_e [2*T_TOK];
__device__ float g_tok_w [2*T_TOK];
__device__ int   g_tok_slot[2*T_TOK];
__device__ int   g_cnt   [NE];
__device__ int   g_cursor[NE];
__device__ int   g_poff  [NE+1];
__device__ int   g_ptotal;

__device__ __forceinline__ float gelu_f(float v) {
    return 0.5f * v * (1.0f + erff(v * 0.7071067811865476f));
}

// ---------------- init: zero counts + pad lists (token 0, weight 0) ----------------
__global__ void init_kernel() {
    int i = blockIdx.x * blockDim.x + threadIdx.x;
    if (i < MAXROWS) { g_rowtok[i] = 0; g_roww[i] = 0.0f; }
    if (i < NE) g_cnt[i] = 0;
}

// ---------------- gate: one warp per token, softmax-top2 (denominator cancels) ----------------
__global__ void gate_kernel(const float* __restrict__ x, const float* __restrict__ gw) {
    int gtid = blockIdx.x * blockDim.x + threadIdx.x;
    int t = gtid >> 5, lane = gtid & 31;
    if (t >= T_TOK) return;
    const float* xr = x + (size_t)t * DH;
    float acc[NE];
#pragma unroll
    for (int e = 0; e < NE; e++) acc[e] = 0.0f;
    for (int i = lane; i < DH; i += 32) {
        float xv = xr[i];
#pragma unroll
        for (int e = 0; e < NE; e++) acc[e] = fmaf(xv, gw[e*DH + i], acc[e]);
    }
#pragma unroll
    for (int e = 0; e < NE; e++) {
#pragma unroll
        for (int o = 16; o > 0; o >>= 1) acc[e] += __shfl_xor_sync(0xffffffffu, acc[e], o);
    }
    if (lane == 0) {
        int i0 = 0;
#pragma unroll
        for (int e = 1; e < NE; e++) if (acc[e] > acc[i0]) i0 = e;
        int i1 = (i0 == 0) ? 1 : 0;
#pragma unroll
        for (int e = 0; e < NE; e++) if (e != i0 && acc[e] > acc[i1]) i1 = e;
        // renormalized top-2 softmax weights: softmax denom cancels
        float e1 = expf(acc[i1] - acc[i0]);   // e0 == 1
        float inv = 1.0f / (1.0f + e1);
        g_tok_e[2*t]   = i0;  g_tok_w[2*t]   = inv;
        g_tok_e[2*t+1] = i1;  g_tok_w[2*t+1] = e1 * inv;
        atomicAdd(&g_cnt[i0], 1);
        atomicAdd(&g_cnt[i1], 1);
    }
}

// ---------------- scan: padded segment offsets ----------------
__global__ void scan_kernel() {
    int off = 0;
    for (int e = 0; e < NE; e++) {
        g_poff[e] = off; g_cursor[e] = off;
        off += ((g_cnt[e] + BM - 1) / BM) * BM;
    }
    g_poff[NE] = off;
    g_ptotal = off;
}

// ---------------- place: build per-expert row lists ----------------
__global__ void place_kernel() {
    int id = blockIdx.x * blockDim.x + threadIdx.x;
    if (id >= 2*T_TOK) return;
    int e = g_tok_e[id];
    int r = atomicAdd(&g_cursor[e], 1);
    g_rowtok[r] = id >> 1;
    g_roww[r]   = g_tok_w[id];
    g_tok_slot[id] = r;
}

// ---------------- SGEMM core, 128x128x16 tile, 8x8 per thread ----------------
// MODE 0: H13 = x @ [w1;w3]^T + b           (M=T,       N=4096, K=768)
// MODE 1: out = Act @ w2^T + b2             (M=T,       N=768,  K=2048)
// MODE 2: Hr  = gelu(gather(x) @ fc1_e^T+b) (M=ptotal,  N=2048, K=768)
// MODE 3: Y   = w * (Hr @ fc2_e^T + b)      (M=ptotal,  N=768,  K=2048)
template<int MODE>
__global__ void __launch_bounds__(256, 2) sgemm_k(
    const float* __restrict__ A,
    const float* __restrict__ B0, const float* __restrict__ B1,
    const float* __restrict__ bias0, const float* __restrict__ bias1,
    float* __restrict__ Cpar)
{
    constexpr int K   = (MODE == 0 || MODE == 2) ? DH : FF;
    constexpr int LDC = (MODE == 0) ? 2*FF : ((MODE == 2) ? FF : DH);

    const int m0 = blockIdx.x * BM;
    const int n0 = blockIdx.y * BN;

    int eidx = 0;
    if (MODE == 2 || MODE == 3) {
        if (m0 >= g_ptotal) return;
        while (m0 >= g_poff[eidx + 1]) eidx++;
    }

    const float* Ap = (MODE == 1) ? g_Act : ((MODE == 3) ? g_Hr : A);
    const float* Bp; const float* bp; int nb = n0;
    if (MODE == 0) {
        if (n0 < FF) { Bp = B0; bp = bias0; }
        else         { Bp = B1; bp = bias1; nb = n0 - FF; }
    } else if (MODE == 1) { Bp = B0; bp = bias0; }
    else if (MODE == 2)   { Bp = B0 + (size_t)eidx * FF * DH; bp = bias0 + eidx * FF; }
    else                  { Bp = B0 + (size_t)eidx * DH * FF; bp = bias0 + eidx * DH; }

    __shared__ float As[BK][BM];
    __shared__ float Bs[BK][BN];
    __shared__ int   s_tok[BM];

    const int tid = threadIdx.x;
    const int ty = tid >> 4, tx = tid & 15;

    if (MODE == 2) {
        if (tid < BM) s_tok[tid] = g_rowtok[m0 + tid];
    }

    float acc[8][8];
#pragma unroll
    for (int i = 0; i < 8; i++)
#pragma unroll
        for (int j = 0; j < 8; j++) acc[i][j] = 0.0f;

    for (int k0 = 0; k0 < K; k0 += BK) {
        __syncthreads();
#pragma unroll
        for (int s = 0; s < 2; s++) {
            int slot = tid + s * 256;
            int r = slot >> 2, kc = (slot & 3) * 4;
            int arow = (MODE == 2) ? s_tok[r] : (m0 + r);
            float4 v = *(const float4*)(Ap + (size_t)arow * K + k0 + kc);
            As[kc+0][r] = v.x; As[kc+1][r] = v.y; As[kc+2][r] = v.z; As[kc+3][r] = v.w;
        }
#pragma unroll
        for (int s = 0; s < 2; s++) {
            int slot = tid + s * 256;
            int r = slot >> 2, kc = (slot & 3) * 4;
            float4 v = *(const float4*)(Bp + (size_t)(nb + r) * K + k0 + kc);
            Bs[kc+0][r] = v.x; Bs[kc+1][r] = v.y; Bs[kc+2][r] = v.z; Bs[kc+3][r] = v.w;
        }
        __syncthreads();
#pragma unroll
        for (int kk = 0; kk < BK; kk++) {
            float ra[8], rb[8];
#pragma unroll
            for (int i = 0; i < 8; i++) ra[i] = As[kk][ty*8 + i];
#pragma unroll
            for (int j = 0; j < 8; j++) rb[j] = Bs[kk][tx*8 + j];
#pragma unroll
            for (int i = 0; i < 8; i++)
#pragma unroll
                for (int j = 0; j < 8; j++) acc[i][j] = fmaf(ra[i], rb[j], acc[i][j]);
        }
    }

    // epilogue
#pragma unroll
    for (int i = 0; i < 8; i++) {
        int row = m0 + ty*8 + i;
        float wscat = 0.0f;
        if (MODE == 3) wscat = g_roww[row];
#pragma unroll
        for (int j = 0; j < 8; j++) {
            int cl = nb + tx*8 + j;                  // local column (bias / B index)
            float v = acc[i][j] + bp[cl];
            if (MODE == 0)      g_H13[(size_t)row * LDC + n0 + tx*8 + j] = v;
            else if (MODE == 1) Cpar [(size_t)row * LDC + cl] = v;
            else if (MODE == 2) g_Hr [(size_t)row * LDC + cl] = gelu_f(v);
            else                g_Y  [(size_t)row * LDC + cl] = wscat * v;
        }
    }
}

// ---------------- gated activation for shared MLP ----------------
__global__ void act_kernel() {
    int i = blockIdx.x * blockDim.x + threadIdx.x;
    if (i >= T_TOK * FF) return;
    int t = i >> 11;               // FF = 2048
    int j = i & (FF - 1);
    float h1 = g_H13[(size_t)t * (2*FF) + j];
    float h3 = g_H13[(size_t)t * (2*FF) + FF + j];
    g_Act[i] = gelu_f(h1) * h3;
}

// ---------------- deterministic combine: out += Y[slot0] + Y[slot1] ----------------
__global__ void combine_kernel(float* __restrict__ out) {
    int i = blockIdx.x * blockDim.x + threadIdx.x;
    if (i >= T_TOK * DH) return;
    int t = i / DH;
    int d = i - t * DH;
    int s0 = g_tok_slot[2*t], s1 = g_tok_slot[2*t + 1];
    out[i] += g_Y[(size_t)s0 * DH + d] + g_Y[(size_t)s1 * DH + d];
}

// ---------------- launch ----------------
extern "C" void kernel_launch(void* const* d_in, const int* in_sizes, int n_in,
                              void* d_out, int out_size) {
    const float* x      = (const float*)d_in[0];
    const float* gate_w = (const float*)d_in[1];
    const float* fc1_w  = (const float*)d_in[2];
    const float* fc1_b  = (const float*)d_in[3];
    const float* fc2_w  = (const float*)d_in[4];
    const float* fc2_b  = (const float*)d_in[5];
    const float* w1_w   = (const float*)d_in[6];
    const float* w1_b   = (const float*)d_in[7];
    const float* w3_w   = (const float*)d_in[8];
    const float* w3_b   = (const float*)d_in[9];
    const float* w2_w   = (const float*)d_in[10];
    const float* w2_b   = (const float*)d_in[11];
    float* out = (float*)d_out;

    init_kernel <<<(MAXROWS + 255) / 256, 256>>>();
    gate_kernel <<<(T_TOK * 32) / 256, 256>>>(x, gate_w);
    scan_kernel <<<1, 1>>>();
    place_kernel<<<(2 * T_TOK) / 256, 256>>>();

    // shared MLP
    sgemm_k<0><<<dim3(T_TOK / BM, (2*FF) / BN), 256>>>(x, w1_w, w3_w, w1_b, w3_b, nullptr);
    act_kernel<<<(T_TOK * FF) / 256, 256>>>();
    sgemm_k<1><<<dim3(T_TOK / BM, DH / BN), 256>>>(nullptr, w2_w, nullptr, w2_b, nullptr, out);

    // routed experts (segment-tiled over padded row lists)
    sgemm_k<2><<<dim3(MAXROWS / BM, FF / BN), 256>>>(x, fc1_w, nullptr, fc1_b, nullptr, nullptr);
    sgemm_k<3><<<dim3(MAXROWS / BM, DH / BN), 256>>>(nullptr, fc2_w, nullptr, fc2_b, nullptr, nullptr);

    combine_kernel<<<(T_TOK * DH) / 256, 256>>>(out);
}

// round 3
// speedup vs baseline: 2.8693x; 2.8693x over previous
#include <cuda_runtime.h>
#include <math.h>
#include <stdint.h>

#define T_TOK 16384
#define DH 768
#define FF 2048
#define NE 8
#define BM 128
#define BN 128
#define BK 32
#define NS 4
#define ROWF 36                       /* 32 floats + 4 pad per staged row */
#define AOFF 0
#define BOFF (128*ROWF)
#define STGF (2*128*ROWF)             /* floats per stage = 9216 (36864 B) */
#define MAXROWS (2*T_TOK + NE*BM)     /* 33792 */

// ---------------- scratch ----------------
__device__ __align__(256) float g_H13[(size_t)T_TOK * 2 * FF];
__device__ __align__(256) float g_Act[(size_t)T_TOK * FF];
__device__ __align__(256) float g_Hr [(size_t)MAXROWS * FF];
__device__ __align__(256) float g_Y  [(size_t)MAXROWS * DH];
__device__ int   g_rowtok[MAXROWS];
__device__ float g_roww  [MAXROWS];
__device__ int   g_tok_e [2*T_TOK];
__device__ float g_tok_w [2*T_TOK];
__device__ int   g_tok_slot[2*T_TOK];
__device__ int   g_cnt   [NE];
__device__ int   g_cursor[NE];
__device__ int   g_poff  [NE+1];
__device__ int   g_ptotal;

__device__ __forceinline__ float gelu_f(float v) {
    return 0.5f * v * (1.0f + erff(v * 0.7071067811865476f));
}

// ---------------- PTX helpers (family-target-safe: sm_80+ only) ----------------
__device__ __forceinline__ uint32_t smem_u32(const void* p) {
    uint32_t a;
    asm("{ .reg .u64 t; cvta.to.shared.u64 t, %1; cvt.u32.u64 %0, t; }" : "=r"(a) : "l"(p));
    return a;
}
__device__ __forceinline__ void cpa16(uint32_t dst, const void* src) {
    asm volatile("cp.async.cg.shared.global [%0], [%1], 16;" :: "r"(dst), "l"(src));
}
__device__ __forceinline__ void cpa_commit() { asm volatile("cp.async.commit_group;"); }
template<int N> __device__ __forceinline__ void cpa_wait() { asm volatile("cp.async.wait_group %0;" :: "n"(N)); }

__device__ __forceinline__ uint32_t f2tf(float v) {
    uint32_t r;
    asm("cvt.rna.tf32.f32 %0, %1;" : "=r"(r) : "f"(v));
    return r;
}
#define MMA_TF32(d, a, b) \
    asm volatile("mma.sync.aligned.m16n8k8.row.col.f32.tf32.tf32.f32 " \
        "{%0,%1,%2,%3}, {%4,%5,%6,%7}, {%8,%9}, {%0,%1,%2,%3};" \
        : "+f"((d)[0]), "+f"((d)[1]), "+f"((d)[2]), "+f"((d)[3]) \
        : "r"((a)[0]), "r"((a)[1]), "r"((a)[2]), "r"((a)[3]), "r"((b)[0]), "r"((b)[1]))

// ---------------- small kernels ----------------
__global__ void init_kernel() {
    int i = blockIdx.x * blockDim.x + threadIdx.x;
    if (i < MAXROWS) { g_rowtok[i] = 0; g_roww[i] = 0.0f; }
    if (i < NE) g_cnt[i] = 0;
}

__global__ void gate_kernel(const float* __restrict__ x, const float* __restrict__ gw) {
    int gtid = blockIdx.x * blockDim.x + threadIdx.x;
    int t = gtid >> 5, lane = gtid & 31;
    if (t >= T_TOK) return;
    const float* xr = x + (size_t)t * DH;
    float acc[NE];
#pragma unroll
    for (int e = 0; e < NE; e++) acc[e] = 0.0f;
    for (int i = lane; i < DH; i += 32) {
        float xv = xr[i];
#pragma unroll
        for (int e = 0; e < NE; e++) acc[e] = fmaf(xv, gw[e*DH + i], acc[e]);
    }
#pragma unroll
    for (int e = 0; e < NE; e++) {
#pragma unroll
        for (int o = 16; o > 0; o >>= 1) acc[e] += __shfl_xor_sync(0xffffffffu, acc[e], o);
    }
    if (lane == 0) {
        int i0 = 0;
#pragma unroll
        for (int e = 1; e < NE; e++) if (acc[e] > acc[i0]) i0 = e;
        int i1 = (i0 == 0) ? 1 : 0;
#pragma unroll
        for (int e = 0; e < NE; e++) if (e != i0 && acc[e] > acc[i1]) i1 = e;
        float e1 = expf(acc[i1] - acc[i0]);
        float inv = 1.0f / (1.0f + e1);
        g_tok_e[2*t]   = i0;  g_tok_w[2*t]   = inv;
        g_tok_e[2*t+1] = i1;  g_tok_w[2*t+1] = e1 * inv;
        atomicAdd(&g_cnt[i0], 1);
        atomicAdd(&g_cnt[i1], 1);
    }
}

__global__ void scan_kernel() {
    int off = 0;
    for (int e = 0; e < NE; e++) {
        g_poff[e] = off; g_cursor[e] = off;
        off += ((g_cnt[e] + BM - 1) / BM) * BM;
    }
    g_poff[NE] = off;
    g_ptotal = off;
}

__global__ void place_kernel() {
    int id = blockIdx.x * blockDim.x + threadIdx.x;
    if (id >= 2*T_TOK) return;
    int e = g_tok_e[id];
    int r = atomicAdd(&g_cursor[e], 1);
    g_rowtok[r] = id >> 1;
    g_roww[r]   = g_tok_w[id];
    g_tok_slot[id] = r;
}

__global__ void act_kernel() {
    int i = blockIdx.x * blockDim.x + threadIdx.x;
    if (i >= T_TOK * FF) return;
    int t = i >> 11;
    int j = i & (FF - 1);
    float h1 = g_H13[(size_t)t * (2*FF) + j];
    float h3 = g_H13[(size_t)t * (2*FF) + FF + j];
    g_Act[i] = gelu_f(h1) * h3;
}

__global__ void combine_kernel(float* __restrict__ out) {
    int i = blockIdx.x * blockDim.x + threadIdx.x;
    if (i >= T_TOK * DH) return;
    int t = i / DH;
    int d = i - t * DH;
    int s0 = g_tok_slot[2*t], s1 = g_tok_slot[2*t + 1];
    out[i] += g_Y[(size_t)s0 * DH + d] + g_Y[(size_t)s1 * DH + d];
}

// ---------------- tf32 mma.sync GEMM, 128x128x32 tile ----------------
// MODE 0: H13 = x @ [w1;w3]^T + b           (M=T,      N=4096, K=768)
// MODE 1: out = Act @ w2^T + b2             (M=T,      N=768,  K=2048)
// MODE 2: Hr  = gelu(gather(x) @ fc1^T + b) (M=ptotal, N=2048, K=768)
// MODE 3: Y   = w * (Hr @ fc2^T + b)        (M=ptotal, N=768,  K=2048)
template<int MODE>
__global__ void __launch_bounds__(256, 1) tgemm(
    const float* __restrict__ A,
    const float* __restrict__ B0, const float* __restrict__ B1,
    const float* __restrict__ bias0, const float* __restrict__ bias1,
    float* __restrict__ Cpar)
{
    constexpr int K   = (MODE == 0 || MODE == 2) ? DH : FF;
    constexpr int LDC = (MODE == 0) ? 2*FF : ((MODE == 2) ? FF : DH);
    constexpr int ns  = K / BK;

    const int m0 = blockIdx.x * BM;
    const int n0 = blockIdx.y * BN;

    int eidx = 0;
    if (MODE == 2 || MODE == 3) {
        if (m0 >= g_ptotal) return;
        while (m0 >= g_poff[eidx + 1]) eidx++;
    }

    const float* Ap = (MODE == 1) ? g_Act : ((MODE == 3) ? g_Hr : A);
    const float* Bp; const float* bp; int nb = n0;
    if (MODE == 0) {
        if (n0 < FF) { Bp = B0; bp = bias0; }
        else         { Bp = B1; bp = bias1; nb = n0 - FF; }
    } else if (MODE == 1) { Bp = B0; bp = bias0; }
    else if (MODE == 2)   { Bp = B0 + (size_t)eidx * FF * DH; bp = bias0 + eidx * FF; }
    else                  { Bp = B0 + (size_t)eidx * DH * FF; bp = bias0 + eidx * DH; }

    extern __shared__ float dsm[];
    __shared__ int   s_tok [BM];
    __shared__ float s_bias[BN];
    __shared__ float s_roww[BM];

    const int tid  = threadIdx.x;
    const int lane = tid & 31;
    const int wid  = tid >> 5;
    const int wm   = wid & 1;          // 2 warps along M (64 rows each)
    const int wn   = wid >> 1;         // 4 warps along N (32 cols each)
    const int gid  = lane >> 2;        // 0..7
    const int qid  = lane & 3;         // 0..3

    if (tid < BM) {
        if (MODE == 2) s_tok [tid] = g_rowtok[m0 + tid];
        if (MODE == 3) s_roww[tid] = g_roww  [m0 + tid];
        s_bias[tid] = bp[nb + tid];
    }
    __syncthreads();

    // -------- stage loader: 2048 x 16B chunks (A 1024 | B 1024) --------
    auto load_stage = [&](int s) {
        const int buf = s & (NS - 1);
        const int k0  = s * BK;
#pragma unroll
        for (int i = 0; i < 8; i++) {
            int c = tid + i * 256;
            if (c < 1024) {
                int r = c >> 3, cw = c & 7;
                int arow = (MODE == 2) ? s_tok[r] : (m0 + r);
                const float* src = Ap + (size_t)arow * K + k0 + cw * 4;
                cpa16(smem_u32(&dsm[buf * STGF + r * ROWF + cw * 4]), src);
            } else {
                int c2 = c - 1024;
                int rn = c2 >> 3, cw = c2 & 7;
                const float* src = Bp + (size_t)(nb + rn) * K + k0 + cw * 4;
                cpa16(smem_u32(&dsm[buf * STGF + BOFF + rn * ROWF + cw * 4]), src);
            }
        }
    };

    float acc[4][4][4];
#pragma unroll
    for (int mt = 0; mt < 4; mt++)
#pragma unroll
        for (int nt = 0; nt < 4; nt++)
#pragma unroll
            for (int r = 0; r < 4; r++) acc[mt][nt][r] = 0.0f;

    load_stage(0); cpa_commit();
    load_stage(1); cpa_commit();
    load_stage(2); cpa_commit();

    for (int s = 0; s < ns; s++) {
        cpa_wait<NS - 2>();
        __syncthreads();
        if (s + NS - 1 < ns) load_stage(s + NS - 1);
        cpa_commit();                       // empty-group commit in the tail keeps wait semantics

        const int buf = s & (NS - 1);
        const float* sA = dsm + buf * STGF;
        const float* sB = sA + BOFF;

#pragma unroll
        for (int k8 = 0; k8 < BK / 8; k8++) {
            const int kb = k8 * 8 + qid;
            uint32_t af[4][4];
#pragma unroll
            for (int mt = 0; mt < 4; mt++) {
                const float* p = sA + (wm * 64 + mt * 16 + gid) * ROWF + kb;
                af[mt][0] = f2tf(p[0]);
                af[mt][1] = f2tf(p[8 * ROWF]);
                af[mt][2] = f2tf(p[4]);
                af[mt][3] = f2tf(p[8 * ROWF + 4]);
            }
            uint32_t bf[4][2];
#pragma unroll
            for (int nt = 0; nt < 4; nt++) {
                const float* p = sB + (wn * 32 + nt * 8 + gid) * ROWF + kb;
                bf[nt][0] = f2tf(p[0]);
                bf[nt][1] = f2tf(p[4]);
            }
#pragma unroll
            for (int mt = 0; mt < 4; mt++)
#pragma unroll
                for (int nt = 0; nt < 4; nt++)
                    MMA_TF32(acc[mt][nt], af[mt], bf[nt]);
        }
    }

    // -------- epilogue: bias/act/weight fused, float2 stores --------
#pragma unroll
    for (int mt = 0; mt < 4; mt++) {
        const int lr0 = wm * 64 + mt * 16 + gid;
        const int lr1 = lr0 + 8;
        const int row0 = m0 + lr0, row1 = m0 + lr1;
        float wmul0 = 1.0f, wmul1 = 1.0f;
        if (MODE == 3) { wmul0 = s_roww[lr0]; wmul1 = s_roww[lr1]; }
#pragma unroll
        for (int nt = 0; nt < 4; nt++) {
            const int cl = wn * 32 + nt * 8 + qid * 2;
            float v00 = acc[mt][nt][0] + s_bias[cl];
            float v01 = acc[mt][nt][1] + s_bias[cl + 1];
            float v10 = acc[mt][nt][2] + s_bias[cl];
            float v11 = acc[mt][nt][3] + s_bias[cl + 1];
            if (MODE == 2) {
                v00 = gelu_f(v00); v01 = gelu_f(v01);
                v10 = gelu_f(v10); v11 = gelu_f(v11);
            }
            if (MODE == 3) {
                v00 *= wmul0; v01 *= wmul0;
                v10 *= wmul1; v11 *= wmul1;
            }
            const int col = n0 + cl;
            float2 o0 = make_float2(v00, v01);
            float2 o1 = make_float2(v10, v11);
            if (MODE == 0) {
                *(float2*)&g_H13[(size_t)row0 * LDC + col] = o0;
                *(float2*)&g_H13[(size_t)row1 * LDC + col] = o1;
            } else if (MODE == 1) {
                *(float2*)&Cpar[(size_t)row0 * LDC + col] = o0;
                *(float2*)&Cpar[(size_t)row1 * LDC + col] = o1;
            } else if (MODE == 2) {
                *(float2*)&g_Hr[(size_t)row0 * LDC + col] = o0;
                *(float2*)&g_Hr[(size_t)row1 * LDC + col] = o1;
            } else {
                *(float2*)&g_Y[(size_t)row0 * LDC + col] = o0;
                *(float2*)&g_Y[(size_t)row1 * LDC + col] = o1;
            }
        }
    }
}

// ---------------- launch ----------------
extern "C" void kernel_launch(void* const* d_in, const int* in_sizes, int n_in,
                              void* d_out, int out_size) {
    const float* x      = (const float*)d_in[0];
    const float* gate_w = (const float*)d_in[1];
    const float* fc1_w  = (const float*)d_in[2];
    const float* fc1_b  = (const float*)d_in[3];
    const float* fc2_w  = (const float*)d_in[4];
    const float* fc2_b  = (const float*)d_in[5];
    const float* w1_w   = (const float*)d_in[6];
    const float* w1_b   = (const float*)d_in[7];
    const float* w3_w   = (const float*)d_in[8];
    const float* w3_b   = (const float*)d_in[9];
    const float* w2_w   = (const float*)d_in[10];
    const float* w2_b   = (const float*)d_in[11];
    float* out = (float*)d_out;

    const int dyn = NS * STGF * 4;    // 147456 bytes
    static int attr_done = 0;
    if (!attr_done) {
        cudaFuncSetAttribute(tgemm<0>, cudaFuncAttributeMaxDynamicSharedMemorySize, dyn);
        cudaFuncSetAttribute(tgemm<1>, cudaFuncAttributeMaxDynamicSharedMemorySize, dyn);
        cudaFuncSetAttribute(tgemm<2>, cudaFuncAttributeMaxDynamicSharedMemorySize, dyn);
        cudaFuncSetAttribute(tgemm<3>, cudaFuncAttributeMaxDynamicSharedMemorySize, dyn);
        attr_done = 1;
    }

    init_kernel <<<(MAXROWS + 255) / 256, 256>>>();
    gate_kernel <<<(T_TOK * 32) / 256, 256>>>(x, gate_w);
    scan_kernel <<<1, 1>>>();
    place_kernel<<<(2 * T_TOK) / 256, 256>>>();

    // shared MLP
    tgemm<0><<<dim3(T_TOK / BM, (2*FF) / BN), 256, dyn>>>(x, w1_w, w3_w, w1_b, w3_b, nullptr);
    act_kernel<<<(T_TOK * FF) / 256, 256>>>();
    tgemm<1><<<dim3(T_TOK / BM, DH / BN), 256, dyn>>>(nullptr, w2_w, nullptr, w2_b, nullptr, out);

    // routed experts
    tgemm<2><<<dim3(MAXROWS / BM, FF / BN), 256, dyn>>>(x, fc1_w, nullptr, fc1_b, nullptr, nullptr);
    tgemm<3><<<dim3(MAXROWS / BM, DH / BN), 256, dyn>>>(nullptr, fc2_w, nullptr, fc2_b, nullptr, nullptr);

    combine_kernel<<<(T_TOK * DH) / 256, 256>>>(out);
}

// round 5
// speedup vs baseline: 3.5388x; 1.2333x over previous
#include <cuda_runtime.h>
#include <math.h>
#include <stdint.h>

#define T_TOK 16384
#define DH 768
#define FF 2048
#define NE 8
#define BM 128
#define BN 128
#define BK 32
#define NS 3
#define ROWF 36                       /* 32 floats + 4 pad per staged row */
#define BOFF (128*ROWF)
#define STGF (2*128*ROWF)             /* floats per stage = 9216 (36864 B) */
#define MAXROWS (2*T_TOK + NE*BM)     /* 33792 */

// ---------------- scratch ----------------
__device__ __align__(256) float g_H13[(size_t)T_TOK * 2 * FF];
__device__ __align__(256) float g_Act[(size_t)T_TOK * FF];
__device__ __align__(256) float g_Hr [(size_t)MAXROWS * FF];
__device__ __align__(256) float g_Y  [(size_t)MAXROWS * DH];
// tf32-prerounded operand copies
__device__ __align__(256) float g_xt  [(size_t)T_TOK * DH];
__device__ __align__(256) float g_fc1t[(size_t)NE * FF * DH];
__device__ __align__(256) float g_fc2t[(size_t)NE * DH * FF];
__device__ __align__(256) float g_w1t [(size_t)FF * DH];
__device__ __align__(256) float g_w3t [(size_t)FF * DH];
__device__ __align__(256) float g_w2t [(size_t)DH * FF];
__device__ int   g_rowtok[MAXROWS];
__device__ float g_roww  [MAXROWS];
__device__ int   g_tok_e [2*T_TOK];
__device__ float g_tok_w [2*T_TOK];
__device__ int   g_tok_slot[2*T_TOK];
__device__ int   g_cnt   [NE];
__device__ int   g_cursor[NE];
__device__ int   g_poff  [NE+1];
__device__ int   g_ptotal;

__device__ __forceinline__ float gelu_f(float v) {
    return 0.5f * v * (1.0f + erff(v * 0.7071067811865476f));
}

// ---------------- PTX helpers (family-target-safe: sm_80+ only) ----------------
__device__ __forceinline__ uint32_t smem_u32(const void* p) {
    uint32_t a;
    asm("{ .reg .u64 t; cvta.to.shared.u64 t, %1; cvt.u32.u64 %0, t; }" : "=r"(a) : "l"(p));
    return a;
}
__device__ __forceinline__ void cpa16(uint32_t dst, const void* src) {
    asm volatile("cp.async.cg.shared.global [%0], [%1], 16;" :: "r"(dst), "l"(src));
}
__device__ __forceinline__ void cpa_commit() { asm volatile("cp.async.commit_group;"); }
template<int N> __device__ __forceinline__ void cpa_wait() { asm volatile("cp.async.wait_group %0;" :: "n"(N)); }

__device__ __forceinline__ float f2tf_f(float v) {
    uint32_t r;
    asm("cvt.rna.tf32.f32 %0, %1;" : "=r"(r) : "f"(v));
    return __uint_as_float(r);
}
#define MMA_TF32(d, a, b) \
    asm volatile("mma.sync.aligned.m16n8k8.row.col.f32.tf32.tf32.f32 " \
        "{%0,%1,%2,%3}, {%4,%5,%6,%7}, {%8,%9}, {%0,%1,%2,%3};" \
        : "+f"((d)[0]), "+f"((d)[1]), "+f"((d)[2]), "+f"((d)[3]) \
        : "r"((a)[0]), "r"((a)[1]), "r"((a)[2]), "r"((a)[3]), "r"((b)[0]), "r"((b)[1]))

// ---------------- small kernels ----------------
__global__ void init_kernel() {
    int i = blockIdx.x * blockDim.x + threadIdx.x;
    if (i < MAXROWS) { g_rowtok[i] = 0; g_roww[i] = 0.0f; }
    if (i < NE) g_cnt[i] = 0;
}

// pre-round all static GEMM operands to tf32 (float4-vectorized, one launch)
#define PC_N0 (T_TOK*DH/4)
#define PC_N1 (PC_N0 + NE*FF*DH/4)
#define PC_N2 (PC_N1 + NE*DH*FF/4)
#define PC_N3 (PC_N2 + FF*DH/4)
#define PC_N4 (PC_N3 + FF*DH/4)
#define PC_N5 (PC_N4 + DH*FF/4)
__global__ void preconv_kernel(const float4* __restrict__ x,  const float4* __restrict__ fc1,
                               const float4* __restrict__ fc2, const float4* __restrict__ w1,
                               const float4* __restrict__ w3,  const float4* __restrict__ w2) {
    for (long i = blockIdx.x * (long)blockDim.x + threadIdx.x; i < PC_N5;
         i += (long)gridDim.x * blockDim.x) {
        const float4* src; float4* dst; long j;
        if (i < PC_N0)      { src = x;   dst = (float4*)g_xt;   j = i; }
        else if (i < PC_N1) { src = fc1; dst = (float4*)g_fc1t; j = i - PC_N0; }
        else if (i < PC_N2) { src = fc2; dst = (float4*)g_fc2t; j = i - PC_N1; }
        else if (i < PC_N3) { src = w1;  dst = (float4*)g_w1t;  j = i - PC_N2; }
        else if (i < PC_N4) { src = w3;  dst = (float4*)g_w3t;  j = i - PC_N3; }
        else                { src = w2;  dst = (float4*)g_w2t;  j = i - PC_N4; }
        float4 v = src[j];
        v.x = f2tf_f(v.x); v.y = f2tf_f(v.y); v.z = f2tf_f(v.z); v.w = f2tf_f(v.w);
        dst[j] = v;
    }
}

__global__ void gate_kernel(const float* __restrict__ x, const float* __restrict__ gw) {
    int gtid = blockIdx.x * blockDim.x + threadIdx.x;
    int t = gtid >> 5, lane = gtid & 31;
    if (t >= T_TOK) return;
    const float* xr = x + (size_t)t * DH;
    float acc[NE];
#pragma unroll
    for (int e = 0; e < NE; e++) acc[e] = 0.0f;
    for (int i = lane; i < DH; i += 32) {
        float xv = xr[i];
#pragma unroll
        for (int e = 0; e < NE; e++) acc[e] = fmaf(xv, gw[e*DH + i], acc[e]);
    }
#pragma unroll
    for (int e = 0; e < NE; e++) {
#pragma unroll
        for (int o = 16; o > 0; o >>= 1) acc[e] += __shfl_xor_sync(0xffffffffu, acc[e], o);
    }
    if (lane == 0) {
        int i0 = 0;
#pragma unroll
        for (int e = 1; e < NE; e++) if (acc[e] > acc[i0]) i0 = e;
        int i1 = (i0 == 0) ? 1 : 0;
#pragma unroll
        for (int e = 0; e < NE; e++) if (e != i0 && acc[e] > acc[i1]) i1 = e;
        float e1 = expf(acc[i1] - acc[i0]);
        float inv = 1.0f / (1.0f + e1);
        g_tok_e[2*t]   = i0;  g_tok_w[2*t]   = inv;
        g_tok_e[2*t+1] = i1;  g_tok_w[2*t+1] = e1 * inv;
        atomicAdd(&g_cnt[i0], 1);
        atomicAdd(&g_cnt[i1], 1);
    }
}

__global__ void scan_kernel() {
    int off = 0;
    for (int e = 0; e < NE; e++) {
        g_poff[e] = off; g_cursor[e] = off;
        off += ((g_cnt[e] + BM - 1) / BM) * BM;
    }
    g_poff[NE] = off;
    g_ptotal = off;
}

__global__ void place_kernel() {
    int id = blockIdx.x * blockDim.x + threadIdx.x;
    if (id >= 2*T_TOK) return;
    int e = g_tok_e[id];
    int r = atomicAdd(&g_cursor[e], 1);
    g_rowtok[r] = id >> 1;
    g_roww[r]   = g_tok_w[id];
    g_tok_slot[id] = r;
}

// gated activation; writes tf32-rounded bits so tgemm<1> loads raw
__global__ void act_kernel() {
    int i = blockIdx.x * blockDim.x + threadIdx.x;
    if (i >= T_TOK * FF) return;
    int t = i >> 11;
    int j = i & (FF - 1);
    float h1 = g_H13[(size_t)t * (2*FF) + j];
    float h3 = g_H13[(size_t)t * (2*FF) + FF + j];
    g_Act[i] = f2tf_f(gelu_f(h1) * h3);
}

__global__ void combine_kernel(float* __restrict__ out) {
    int i = blockIdx.x * blockDim.x + threadIdx.x;
    if (i >= T_TOK * DH) return;
    int t = i / DH;
    int d = i - t * DH;
    int s0 = g_tok_slot[2*t], s1 = g_tok_slot[2*t + 1];
    out[i] += g_Y[(size_t)s0 * DH + d] + g_Y[(size_t)s1 * DH + d];
}

// ---------------- tf32 mma.sync GEMM, 128x128x32 tile, operands pre-rounded ----------------
// All scratch operand pointers resolved IN DEVICE CODE (device symbols are
// only valid device-side; passing them from host passes the shadow address).
// MODE 0: H13 = xt @ [w1t;w3t]^T + b            (M=T,      N=4096, K=768)
// MODE 1: out = Act @ w2t^T + b2                (M=T,      N=768,  K=2048)
// MODE 2: Hr  = tf32(gelu(gather(xt)@fc1t^T+b)) (M=ptot,   N=2048, K=768)
// MODE 3: Y   = w * (Hr @ fc2t^T + b)           (M=ptotal, N=768,  K=2048)
template<int MODE>
__global__ void __launch_bounds__(256, 2) tgemm(
    const float* __restrict__ bias0, const float* __restrict__ bias1,
    float* __restrict__ Cpar)
{
    constexpr int K   = (MODE == 0 || MODE == 2) ? DH : FF;
    constexpr int LDC = (MODE == 0) ? 2*FF : ((MODE == 2) ? FF : DH);
    constexpr int ns  = K / BK;

    const int m0 = blockIdx.x * BM;
    const int n0 = blockIdx.y * BN;

    int eidx = 0;
    if (MODE == 2 || MODE == 3) {
        if (m0 >= g_ptotal) return;
        while (m0 >= g_poff[eidx + 1]) eidx++;
    }

    const float* Ap;
    const float* Bp;
    const float* bp;
    int nb = n0;
    if (MODE == 0) {
        Ap = g_xt;
        if (n0 < FF) { Bp = g_w1t; bp = bias0; }
        else         { Bp = g_w3t; bp = bias1; nb = n0 - FF; }
    } else if (MODE == 1) {
        Ap = g_Act; Bp = g_w2t; bp = bias0;
    } else if (MODE == 2) {
        Ap = g_xt;
        Bp = g_fc1t + (size_t)eidx * FF * DH;
        bp = bias0 + eidx * FF;
    } else {
        Ap = g_Hr;
        Bp = g_fc2t + (size_t)eidx * DH * FF;
        bp = bias0 + eidx * DH;
    }

    extern __shared__ float dsm[];
    __shared__ int   s_tok [BM];
    __shared__ float s_bias[BN];
    __shared__ float s_roww[BM];

    const int tid  = threadIdx.x;
    const int lane = tid & 31;
    const int wid  = tid >> 5;
    const int wm   = wid & 1;          // 2 warps along M (64 rows each)
    const int wn   = wid >> 1;         // 4 warps along N (32 cols each)
    const int gid  = lane >> 2;        // 0..7
    const int qid  = lane & 3;         // 0..3

    if (tid < BM) {
        if (MODE == 2) s_tok [tid] = g_rowtok[m0 + tid];
        if (MODE == 3) s_roww[tid] = g_roww  [m0 + tid];
        s_bias[tid] = bp[nb + tid];
    }
    __syncthreads();

    // -------- stage loader: 2048 x 16B chunks (A 1024 | B 1024) --------
    auto load_stage = [&](int s) {
        const int buf = s % NS;
        const int k0  = s * BK;
#pragma unroll
        for (int i = 0; i < 8; i++) {
            int c = tid + i * 256;
            if (c < 1024) {
                int r = c >> 3, cw = c & 7;
                int arow = (MODE == 2) ? s_tok[r] : (m0 + r);
                const float* src = Ap + (size_t)arow * K + k0 + cw * 4;
                cpa16(smem_u32(&dsm[buf * STGF + r * ROWF + cw * 4]), src);
            } else {
                int c2 = c - 1024;
                int rn = c2 >> 3, cw = c2 & 7;
                const float* src = Bp + (size_t)(nb + rn) * K + k0 + cw * 4;
                cpa16(smem_u32(&dsm[buf * STGF + BOFF + rn * ROWF + cw * 4]), src);
            }
        }
    };

    float acc[4][4][4];
#pragma unroll
    for (int mt = 0; mt < 4; mt++)
#pragma unroll
        for (int nt = 0; nt < 4; nt++)
#pragma unroll
            for (int r = 0; r < 4; r++) acc[mt][nt][r] = 0.0f;

    load_stage(0); cpa_commit();
    load_stage(1); cpa_commit();

    for (int s = 0; s < ns; s++) {
        cpa_wait<NS - 2>();
        __syncthreads();
        if (s + NS - 1 < ns) load_stage(s + NS - 1);
        cpa_commit();                       // empty-group commit keeps wait semantics in tail

        const int buf = s % NS;
        const uint32_t* sA = (const uint32_t*)(dsm + buf * STGF);
        const uint32_t* sB = sA + BOFF;

#pragma unroll
        for (int k8 = 0; k8 < BK / 8; k8++) {
            const int kb = k8 * 8 + qid;
            uint32_t af[4][4];
#pragma unroll
            for (int mt = 0; mt < 4; mt++) {
                const uint32_t* p = sA + (wm * 64 + mt * 16 + gid) * ROWF + kb;
                af[mt][0] = p[0];
                af[mt][1] = p[8 * ROWF];
                af[mt][2] = p[4];
                af[mt][3] = p[8 * ROWF + 4];
            }
            uint32_t bf[4][2];
#pragma unroll
            for (int nt = 0; nt < 4; nt++) {
                const uint32_t* p = sB + (wn * 32 + nt * 8 + gid) * ROWF + kb;
                bf[nt][0] = p[0];
                bf[nt][1] = p[4];
            }
#pragma unroll
            for (int mt = 0; mt < 4; mt++)
#pragma unroll
                for (int nt = 0; nt < 4; nt++)
                    MMA_TF32(acc[mt][nt], af[mt], bf[nt]);
        }
    }

    // -------- epilogue: bias/act/weight fused, float2 stores --------
#pragma unroll
    for (int mt = 0; mt < 4; mt++) {
        const int lr0 = wm * 64 + mt * 16 + gid;
        const int lr1 = lr0 + 8;
        const int row0 = m0 + lr0, row1 = m0 + lr1;
        float wmul0 = 1.0f, wmul1 = 1.0f;
        if (MODE == 3) { wmul0 = s_roww[lr0]; wmul1 = s_roww[lr1]; }
#pragma unroll
        for (int nt = 0; nt < 4; nt++) {
            const int cl = wn * 32 + nt * 8 + qid * 2;
            float v00 = acc[mt][nt][0] + s_bias[cl];
            float v01 = acc[mt][nt][1] + s_bias[cl + 1];
            float v10 = acc[mt][nt][2] + s_bias[cl];
            float v11 = acc[mt][nt][3] + s_bias[cl + 1];
            if (MODE == 2) {   // gelu then tf32-round: tgemm<3> loads raw bits
                v00 = f2tf_f(gelu_f(v00)); v01 = f2tf_f(gelu_f(v01));
                v10 = f2tf_f(gelu_f(v10)); v11 = f2tf_f(gelu_f(v11));
            }
            if (MODE == 3) {
                v00 *= wmul0; v01 *= wmul0;
                v10 *= wmul1; v11 *= wmul1;
            }
            const int col = n0 + cl;
            float2 o0 = make_float2(v00, v01);
            float2 o1 = make_float2(v10, v11);
            if (MODE == 0) {
                *(float2*)&g_H13[(size_t)row0 * LDC + col] = o0;
                *(float2*)&g_H13[(size_t)row1 * LDC + col] = o1;
            } else if (MODE == 1) {
                *(float2*)&Cpar[(size_t)row0 * LDC + col] = o0;
                *(float2*)&Cpar[(size_t)row1 * LDC + col] = o1;
            } else if (MODE == 2) {
                *(float2*)&g_Hr[(size_t)row0 * LDC + col] = o0;
                *(float2*)&g_Hr[(size_t)row1 * LDC + col] = o1;
            } else {
                *(float2*)&g_Y[(size_t)row0 * LDC + col] = o0;
                *(float2*)&g_Y[(size_t)row1 * LDC + col] = o1;
            }
        }
    }
}

// ---------------- launch ----------------
extern "C" void kernel_launch(void* const* d_in, const int* in_sizes, int n_in,
                              void* d_out, int out_size) {
    const float* x      = (const float*)d_in[0];
    const float* gate_w = (const float*)d_in[1];
    const float* fc1_b  = (const float*)d_in[3];
    const float* fc2_b  = (const float*)d_in[5];
    const float* w1_b   = (const float*)d_in[7];
    const float* w3_b   = (const float*)d_in[9];
    const float* w2_b   = (const float*)d_in[11];
    float* out = (float*)d_out;

    const int dyn = NS * STGF * 4;    // 110592 bytes -> 2 CTA/SM
    cudaFuncSetAttribute(tgemm<0>, cudaFuncAttributeMaxDynamicSharedMemorySize, dyn);
    cudaFuncSetAttribute(tgemm<1>, cudaFuncAttributeMaxDynamicSharedMemorySize, dyn);
    cudaFuncSetAttribute(tgemm<2>, cudaFuncAttributeMaxDynamicSharedMemorySize, dyn);
    cudaFuncSetAttribute(tgemm<3>, cudaFuncAttributeMaxDynamicSharedMemorySize, dyn);

    // launch order puts tgemm<2> (biggest GEMM) at index 5 for ncu -s 5 -c 1
    init_kernel   <<<(MAXROWS + 255) / 256, 256>>>();                                   // 0
    preconv_kernel<<<2048, 256>>>((const float4*)x, (const float4*)d_in[2],
                                  (const float4*)d_in[4], (const float4*)d_in[6],
                                  (const float4*)d_in[8], (const float4*)d_in[10]);     // 1
    gate_kernel   <<<(T_TOK * 32) / 256, 256>>>(x, gate_w);                             // 2
    scan_kernel   <<<1, 1>>>();                                                         // 3
    place_kernel  <<<(2 * T_TOK) / 256, 256>>>();                                       // 4

    tgemm<2><<<dim3(MAXROWS / BM, FF / BN), 256, dyn>>>(fc1_b, nullptr, nullptr);       // 5
    tgemm<0><<<dim3(T_TOK / BM, (2*FF) / BN), 256, dyn>>>(w1_b, w3_b, nullptr);         // 6
    act_kernel<<<(T_TOK * FF) / 256, 256>>>();                                          // 7
    tgemm<1><<<dim3(T_TOK / BM, DH / BN), 256, dyn>>>(w2_b, nullptr, out);              // 8
    tgemm<3><<<dim3(MAXROWS / BM, DH / BN), 256, dyn>>>(fc2_b, nullptr, nullptr);       // 9
    combine_kernel<<<(T_TOK * DH) / 256, 256>>>(out);                                   // 10
}

// round 6
// speedup vs baseline: 7.7260x; 2.1832x over previous
#include <cuda_runtime.h>
#include <cuda_fp16.h>
#include <math.h>
#include <stdint.h>

#define T_TOK 16384
#define DH 768
#define FF 2048
#define NE 8
#define BM 128
#define BN 128
#define BK 64
#define NS 3
#define STAGE_B 32768                 /* A 16KB + B 16KB per stage */
#define MAXROWS (2*T_TOK + NE*BM)     /* 33792 */

// ---------------- scratch ----------------
__device__ __align__(256) __half g_H13h[(size_t)T_TOK * 2 * FF];
__device__ __align__(256) __half g_Acth[(size_t)T_TOK * FF];
__device__ __align__(256) __half g_Hrh [(size_t)MAXROWS * FF];
__device__ __align__(256) float  g_Y   [(size_t)MAXROWS * DH];
// fp16 operand copies
__device__ __align__(256) __half g_xh  [(size_t)T_TOK * DH];
__device__ __align__(256) __half g_fc1h[(size_t)NE * FF * DH];
__device__ __align__(256) __half g_fc2h[(size_t)NE * DH * FF];
__device__ __align__(256) __half g_w1h [(size_t)FF * DH];
__device__ __align__(256) __half g_w3h [(size_t)FF * DH];
__device__ __align__(256) __half g_w2h [(size_t)DH * FF];
__device__ int   g_rowtok[MAXROWS];
__device__ float g_roww  [MAXROWS];
__device__ int   g_tok_e [2*T_TOK];
__device__ float g_tok_w [2*T_TOK];
__device__ int   g_tok_slot[2*T_TOK];
__device__ int   g_cnt   [NE];
__device__ int   g_cursor[NE];
__device__ int   g_poff  [NE+1];
__device__ int   g_ptotal;

__device__ __forceinline__ float gelu_f(float v) {
    return 0.5f * v * (1.0f + erff(v * 0.7071067811865476f));
}

// ---------------- PTX helpers (sm_75+/sm_80+ only: family-target-safe) ----------------
__device__ __forceinline__ uint32_t smem_u32(const void* p) {
    uint32_t a;
    asm("{ .reg .u64 t; cvta.to.shared.u64 t, %1; cvt.u32.u64 %0, t; }" : "=r"(a) : "l"(p));
    return a;
}
__device__ __forceinline__ void cpa16(uint32_t dst, const void* src) {
    asm volatile("cp.async.cg.shared.global [%0], [%1], 16;" :: "r"(dst), "l"(src));
}
__device__ __forceinline__ void cpa_commit() { asm volatile("cp.async.commit_group;"); }
template<int N> __device__ __forceinline__ void cpa_wait() { asm volatile("cp.async.wait_group %0;" :: "n"(N)); }

#define LDSM_X4(r0, r1, r2, r3, addr) \
    asm volatile("ldmatrix.sync.aligned.m8n8.x4.shared.b16 {%0,%1,%2,%3}, [%4];" \
        : "=r"(r0), "=r"(r1), "=r"(r2), "=r"(r3) : "r"(addr))

#define MMA_F16(d, a, b) \
    asm volatile("mma.sync.aligned.m16n8k16.row.col.f32.f16.f16.f32 " \
        "{%0,%1,%2,%3}, {%4,%5,%6,%7}, {%8,%9}, {%0,%1,%2,%3};" \
        : "+f"((d)[0]), "+f"((d)[1]), "+f"((d)[2]), "+f"((d)[3]) \
        : "r"((a)[0]), "r"((a)[1]), "r"((a)[2]), "r"((a)[3]), "r"((b)[0]), "r"((b)[1]))

// ---------------- small kernels ----------------
__global__ void init_kernel() {
    int i = blockIdx.x * blockDim.x + threadIdx.x;
    if (i < MAXROWS) { g_rowtok[i] = 0; g_roww[i] = 0.0f; }
    if (i < NE) g_cnt[i] = 0;
}

// convert all static GEMM operands fp32 -> fp16 (float4 loads, half2 stores)
#define PC_N0 (T_TOK*DH/4)
#define PC_N1 (PC_N0 + NE*FF*DH/4)
#define PC_N2 (PC_N1 + NE*DH*FF/4)
#define PC_N3 (PC_N2 + FF*DH/4)
#define PC_N4 (PC_N3 + FF*DH/4)
#define PC_N5 (PC_N4 + DH*FF/4)
__global__ void preconv_kernel(const float4* __restrict__ x,  const float4* __restrict__ fc1,
                               const float4* __restrict__ fc2, const float4* __restrict__ w1,
                               const float4* __restrict__ w3,  const float4* __restrict__ w2) {
    for (long i = blockIdx.x * (long)blockDim.x + threadIdx.x; i < PC_N5;
         i += (long)gridDim.x * blockDim.x) {
        const float4* src; half2* dst; long j;
        if (i < PC_N0)      { src = x;   dst = (half2*)g_xh;   j = i; }
        else if (i < PC_N1) { src = fc1; dst = (half2*)g_fc1h; j = i - PC_N0; }
        else if (i < PC_N2) { src = fc2; dst = (half2*)g_fc2h; j = i - PC_N1; }
        else if (i < PC_N3) { src = w1;  dst = (half2*)g_w1h;  j = i - PC_N2; }
        else if (i < PC_N4) { src = w3;  dst = (half2*)g_w3h;  j = i - PC_N3; }
        else                { src = w2;  dst = (half2*)g_w2h;  j = i - PC_N4; }
        float4 v = src[j];
        dst[j*2]   = __floats2half2_rn(v.x, v.y);
        dst[j*2+1] = __floats2half2_rn(v.z, v.w);
    }
}

__global__ void gate_kernel(const float* __restrict__ x, const float* __restrict__ gw) {
    int gtid = blockIdx.x * blockDim.x + threadIdx.x;
    int t = gtid >> 5, lane = gtid & 31;
    if (t >= T_TOK) return;
    const float* xr = x + (size_t)t * DH;
    float acc[NE];
#pragma unroll
    for (int e = 0; e < NE; e++) acc[e] = 0.0f;
    for (int i = lane; i < DH; i += 32) {
        float xv = xr[i];
#pragma unroll
        for (int e = 0; e < NE; e++) acc[e] = fmaf(xv, gw[e*DH + i], acc[e]);
    }
#pragma unroll
    for (int e = 0; e < NE; e++) {
#pragma unroll
        for (int o = 16; o > 0; o >>= 1) acc[e] += __shfl_xor_sync(0xffffffffu, acc[e], o);
    }
    if (lane == 0) {
        int i0 = 0;
#pragma unroll
        for (int e = 1; e < NE; e++) if (acc[e] > acc[i0]) i0 = e;
        int i1 = (i0 == 0) ? 1 : 0;
#pragma unroll
        for (int e = 0; e < NE; e++) if (e != i0 && acc[e] > acc[i1]) i1 = e;
        float e1 = expf(acc[i1] - acc[i0]);
        float inv = 1.0f / (1.0f + e1);
        g_tok_e[2*t]   = i0;  g_tok_w[2*t]   = inv;
        g_tok_e[2*t+1] = i1;  g_tok_w[2*t+1] = e1 * inv;
        atomicAdd(&g_cnt[i0], 1);
        atomicAdd(&g_cnt[i1], 1);
    }
}

__global__ void scan_kernel() {
    int off = 0;
    for (int e = 0; e < NE; e++) {
        g_poff[e] = off; g_cursor[e] = off;
        off += ((g_cnt[e] + BM - 1) / BM) * BM;
    }
    g_poff[NE] = off;
    g_ptotal = off;
}

__global__ void place_kernel() {
    int id = blockIdx.x * blockDim.x + threadIdx.x;
    if (id >= 2*T_TOK) return;
    int e = g_tok_e[id];
    int r = atomicAdd(&g_cursor[e], 1);
    g_rowtok[r] = id >> 1;
    g_roww[r]   = g_tok_w[id];
    g_tok_slot[id] = r;
}

// gated activation: fp16 in, fp16 out (half2 vectorized)
__global__ void act_kernel() {
    int i = blockIdx.x * blockDim.x + threadIdx.x;
    if (i >= T_TOK * FF / 2) return;
    int t = i >> 10;                 // FF/2 = 1024
    int j = (i & 1023) * 2;
    float2 h1 = __half22float2(*(const half2*)&g_H13h[(size_t)t * (2*FF) + j]);
    float2 h3 = __half22float2(*(const half2*)&g_H13h[(size_t)t * (2*FF) + FF + j]);
    *(half2*)&g_Acth[(size_t)t * FF + j] =
        __floats2half2_rn(gelu_f(h1.x) * h3.x, gelu_f(h1.y) * h3.y);
}

__global__ void combine_kernel(float* __restrict__ out) {
    int i = blockIdx.x * blockDim.x + threadIdx.x;
    if (i >= T_TOK * DH) return;
    int t = i / DH;
    int d = i - t * DH;
    int s0 = g_tok_slot[2*t], s1 = g_tok_slot[2*t + 1];
    out[i] += g_Y[(size_t)s0 * DH + d] + g_Y[(size_t)s1 * DH + d];
}

// ---------------- fp16 mma.sync GEMM, 128x128x64 tile, ldmatrix + XOR swizzle ----------------
// MODE 0: H13h = xh @ [w1h;w3h]^T + b          (M=T,      N=4096, K=768)
// MODE 1: out  = Acth @ w2h^T + b2             (M=T,      N=768,  K=2048)
// MODE 2: Hrh  = fp16(gelu(gather(xh)@fc1h^T+b)) (M=ptot, N=2048, K=768)
// MODE 3: Y    = w * (Hrh @ fc2h^T + b)        (M=ptotal, N=768,  K=2048)
template<int MODE>
__global__ void __launch_bounds__(256, 2) tgemm(
    const float* __restrict__ bias0, const float* __restrict__ bias1,
    float* __restrict__ Cpar)
{
    constexpr int K   = (MODE == 0 || MODE == 2) ? DH : FF;
    constexpr int LDC = (MODE == 0) ? 2*FF : ((MODE == 2) ? FF : DH);
    constexpr int ns  = K / BK;

    const int m0 = blockIdx.x * BM;
    const int n0 = blockIdx.y * BN;

    int eidx = 0;
    if (MODE == 2 || MODE == 3) {
        if (m0 >= g_ptotal) return;
        while (m0 >= g_poff[eidx + 1]) eidx++;
    }

    const __half* Ah;
    const __half* Bh;
    const float* bp;
    int nb = n0;
    if (MODE == 0) {
        Ah = g_xh;
        if (n0 < FF) { Bh = g_w1h; bp = bias0; }
        else         { Bh = g_w3h; bp = bias1; nb = n0 - FF; }
    } else if (MODE == 1) {
        Ah = g_Acth; Bh = g_w2h; bp = bias0;
    } else if (MODE == 2) {
        Ah = g_xh;
        Bh = g_fc1h + (size_t)eidx * FF * DH;
        bp = bias0 + eidx * FF;
    } else {
        Ah = g_Hrh;
        Bh = g_fc2h + (size_t)eidx * DH * FF;
        bp = bias0 + eidx * DH;
    }

    extern __shared__ char dsm[];
    __shared__ int   s_tok [BM];
    __shared__ float s_bias[BN];
    __shared__ float s_roww[BM];

    const int tid  = threadIdx.x;
    const int lane = tid & 31;
    const int wid  = tid >> 5;
    const int wm   = wid & 1;          // 2 warps along M (64 rows each)
    const int wn   = wid >> 1;         // 4 warps along N (32 cols each)
    const int gid  = lane >> 2;        // 0..7
    const int qid  = lane & 3;         // 0..3

    if (tid < BM) {
        if (MODE == 2) s_tok [tid] = g_rowtok[m0 + tid];
        if (MODE == 3) s_roww[tid] = g_roww  [m0 + tid];
        s_bias[tid] = bp[nb + tid];
    }
    __syncthreads();

    const uint32_t smem_base = smem_u32(dsm);

    // -------- stage loader: 2048 x 16B chunks (A 1024 | B 1024), XOR-swizzled rows --------
    // stage row layout: 64 fp16 = 128 B per row; chunk c (8 fp16) at ((c ^ (row&7)) * 16)
    auto load_stage = [&](int s) {
        const uint32_t sb = smem_base + (uint32_t)(s % NS) * STAGE_B;
        const int k0 = s * BK;
#pragma unroll
        for (int i = 0; i < 8; i++) {
            int c = tid + i * 256;
            if (c < 1024) {
                int r = c >> 3, ch = c & 7;
                int arow = (MODE == 2) ? s_tok[r] : (m0 + r);
                const __half* src = Ah + (size_t)arow * K + k0 + ch * 8;
                cpa16(sb + (uint32_t)(r * 128 + ((ch ^ (r & 7)) << 4)), src);
            } else {
                int c2 = c - 1024;
                int rn = c2 >> 3, ch = c2 & 7;
                const __half* src = Bh + (size_t)(nb + rn) * K + k0 + ch * 8;
                cpa16(sb + (uint32_t)(16384 + rn * 128 + ((ch ^ (rn & 7)) << 4)), src);
            }
        }
    };

    // per-thread ldmatrix row bases (stage-relative)
    uint32_t a_base[4], a_xor[4];
#pragma unroll
    for (int mt = 0; mt < 4; mt++) {
        int r = wm * 64 + mt * 16 + (lane & 15);
        a_base[mt] = (uint32_t)(r * 128);
        a_xor[mt]  = (uint32_t)(r & 7);
    }
    const uint32_t a_hi = (uint32_t)(lane >> 4);        // 0: k0-7 chunk, 1: k8-15 chunk
    uint32_t b_base[2], b_xor[2];
#pragma unroll
    for (int p = 0; p < 2; p++) {
        int nr = wn * 32 + p * 16 + ((lane >> 4) << 3) + (lane & 7);
        b_base[p] = (uint32_t)(16384 + nr * 128);
        b_xor[p]  = (uint32_t)(nr & 7);
    }
    const uint32_t b_hi = (uint32_t)((lane >> 3) & 1);

    float acc[4][4][4];
#pragma unroll
    for (int mt = 0; mt < 4; mt++)
#pragma unroll
        for (int nt = 0; nt < 4; nt++)
#pragma unroll
            for (int r = 0; r < 4; r++) acc[mt][nt][r] = 0.0f;

    load_stage(0); cpa_commit();
    load_stage(1); cpa_commit();

    for (int s = 0; s < ns; s++) {
        cpa_wait<NS - 2>();
        __syncthreads();
        if (s + NS - 1 < ns) load_stage(s + NS - 1);
        cpa_commit();                       // empty-group commit keeps wait semantics in tail

        const uint32_t sb = smem_base + (uint32_t)(s % NS) * STAGE_B;

#pragma unroll
        for (int kk = 0; kk < BK / 16; kk++) {
            const uint32_t cha = (uint32_t)(kk * 2) + a_hi;
            const uint32_t chb = (uint32_t)(kk * 2) + b_hi;
            uint32_t af[4][4];
#pragma unroll
            for (int mt = 0; mt < 4; mt++) {
                uint32_t addr = sb + a_base[mt] + ((cha ^ a_xor[mt]) << 4);
                LDSM_X4(af[mt][0], af[mt][1], af[mt][2], af[mt][3], addr);
            }
            uint32_t bf[4][2];
#pragma unroll
            for (int p = 0; p < 2; p++) {
                uint32_t addr = sb + b_base[p] + ((chb ^ b_xor[p]) << 4);
                LDSM_X4(bf[2*p][0], bf[2*p][1], bf[2*p+1][0], bf[2*p+1][1], addr);
            }
#pragma unroll
            for (int mt = 0; mt < 4; mt++)
#pragma unroll
                for (int nt = 0; nt < 4; nt++)
                    MMA_F16(acc[mt][nt], af[mt], bf[nt]);
        }
    }

    // -------- epilogue: bias/act/weight fused --------
#pragma unroll
    for (int mt = 0; mt < 4; mt++) {
        const int lr0 = wm * 64 + mt * 16 + gid;
        const int lr1 = lr0 + 8;
        const int row0 = m0 + lr0, row1 = m0 + lr1;
        float wmul0 = 1.0f, wmul1 = 1.0f;
        if (MODE == 3) { wmul0 = s_roww[lr0]; wmul1 = s_roww[lr1]; }
#pragma unroll
        for (int nt = 0; nt < 4; nt++) {
            const int cl = wn * 32 + nt * 8 + qid * 2;
            float v00 = acc[mt][nt][0] + s_bias[cl];
            float v01 = acc[mt][nt][1] + s_bias[cl + 1];
            float v10 = acc[mt][nt][2] + s_bias[cl];
            float v11 = acc[mt][nt][3] + s_bias[cl + 1];
            const int col = n0 + cl;
            if (MODE == 0) {
                *(half2*)&g_H13h[(size_t)row0 * LDC + col] = __floats2half2_rn(v00, v01);
                *(half2*)&g_H13h[(size_t)row1 * LDC + col] = __floats2half2_rn(v10, v11);
            } else if (MODE == 1) {
                *(float2*)&Cpar[(size_t)row0 * LDC + col] = make_float2(v00, v01);
                *(float2*)&Cpar[(size_t)row1 * LDC + col] = make_float2(v10, v11);
            } else if (MODE == 2) {
                *(half2*)&g_Hrh[(size_t)row0 * LDC + col] =
                    __floats2half2_rn(gelu_f(v00), gelu_f(v01));
                *(half2*)&g_Hrh[(size_t)row1 * LDC + col] =
                    __floats2half2_rn(gelu_f(v10), gelu_f(v11));
            } else {
                *(float2*)&g_Y[(size_t)row0 * LDC + col] = make_float2(v00 * wmul0, v01 * wmul0);
                *(float2*)&g_Y[(size_t)row1 * LDC + col] = make_float2(v10 * wmul1, v11 * wmul1);
            }
        }
    }
}

// ---------------- launch ----------------
extern "C" void kernel_launch(void* const* d_in, const int* in_sizes, int n_in,
                              void* d_out, int out_size) {
    const float* x      = (const float*)d_in[0];
    const float* gate_w = (const float*)d_in[1];
    const float* fc1_b  = (const float*)d_in[3];
    const float* fc2_b  = (const float*)d_in[5];
    const float* w1_b   = (const float*)d_in[7];
    const float* w3_b   = (const float*)d_in[9];
    const float* w2_b   = (const float*)d_in[11];
    float* out = (float*)d_out;

    const int dyn = NS * STAGE_B;     // 98304 bytes -> 2 CTA/SM
    cudaFuncSetAttribute(tgemm<0>, cudaFuncAttributeMaxDynamicSharedMemorySize, dyn);
    cudaFuncSetAttribute(tgemm<1>, cudaFuncAttributeMaxDynamicSharedMemorySize, dyn);
    cudaFuncSetAttribute(tgemm<2>, cudaFuncAttributeMaxDynamicSharedMemorySize, dyn);
    cudaFuncSetAttribute(tgemm<3>, cudaFuncAttributeMaxDynamicSharedMemorySize, dyn);

    // shared-MLP chain first so tgemm<1> lands at my launch index 3 (the slot ncu captures)
    preconv_kernel<<<2048, 256>>>((const float4*)x, (const float4*)d_in[2],
                                  (const float4*)d_in[4], (const float4*)d_in[6],
                                  (const float4*)d_in[8], (const float4*)d_in[10]);     // 0
    tgemm<0><<<dim3(T_TOK / BM, (2*FF) / BN), 256, dyn>>>(w1_b, w3_b, nullptr);         // 1
    act_kernel<<<(T_TOK * FF / 2) / 256, 256>>>();                                      // 2
    tgemm<1><<<dim3(T_TOK / BM, DH / BN), 256, dyn>>>(w2_b, nullptr, out);              // 3

    // routing + routed experts
    init_kernel   <<<(MAXROWS + 255) / 256, 256>>>();                                   // 4
    gate_kernel   <<<(T_TOK * 32) / 256, 256>>>(x, gate_w);                             // 5
    scan_kernel   <<<1, 1>>>();                                                         // 6
    place_kernel  <<<(2 * T_TOK) / 256, 256>>>();                                       // 7
    tgemm<2><<<dim3(MAXROWS / BM, FF / BN), 256, dyn>>>(fc1_b, nullptr, nullptr);       // 8
    tgemm<3><<<dim3(MAXROWS / BM, DH / BN), 256, dyn>>>(fc2_b, nullptr, nullptr);       // 9
    combine_kernel<<<(T_TOK * DH) / 256, 256>>>(out);                                   // 10
}